// round 1
// baseline (speedup 1.0000x reference)
#include <cuda_runtime.h>

#define NN 50000
#define EE 1250000
#define HH 64
#define BB 500
#define BN_EPS 1e-5f

// ---------------- device scratch (static allocation: allowed) ----------------
__device__ float g_d2p[(long)EE * HH];   // 320 MB: pre-BN d2 per edge
__device__ float g_h[NN * HH];           // current node features
__device__ float g_agg[NN * HH];         // gconv accumulator
__device__ float g_hg[BB * HH];          // per-graph global sum
__device__ float g_y1[NN * 64];
__device__ float g_y2[NN * 32];
__device__ float g_red[22592];           // replicated stat sums
__device__ float g_coef[1024];           // affine coefs

// g_red slot offsets (32 replicas each, layout r*2F + {sum[F], sq[F]})
#define OFF_X   0        // F=1
#define OFF_D2  64       // F=64
#define OFF_C1  4160
#define OFF_C2  8256
#define OFF_C3  12352
#define OFF_O1  16448
#define OFF_O2  20544    // F=32

// g_coef offsets
// 0:a[64] 64:c[64] (d1 fused affine)  128:s2 192:t2 (d2 BN)
// 256/320 L1, 384/448 L2, 512/576 L3, 640/704 O1, 768/832 O2 (scale/shift)

__device__ __forceinline__ float sp(float x) {
    float t, l;
    asm("ex2.approx.ftz.f32 %0, %1;" : "=f"(t) : "f"(x * 1.44269504f));
    asm("lg2.approx.f32 %0, %1;" : "=f"(l) : "f"(1.0f + t));
    float r = l * 0.69314718f;
    return x > 20.0f ? x : r;
}

// ---------------- kernels ----------------

__global__ void kzero() {
    int i = blockIdx.x * 256 + threadIdx.x;
    if (i < 22592) g_red[i] = 0.0f;
    if (i < BB * HH) g_hg[i] = 0.0f;
}

__global__ void kxstat(const float* __restrict__ x) {
    float s = 0.f, q = 0.f;
    for (int i = blockIdx.x * blockDim.x + threadIdx.x; i < EE; i += gridDim.x * blockDim.x) {
        float v = x[i];
        s += v; q += v * v;
    }
    __shared__ float ss[256], sq[256];
    ss[threadIdx.x] = s; sq[threadIdx.x] = q;
    __syncthreads();
    for (int o = 128; o > 0; o >>= 1) {
        if (threadIdx.x < o) { ss[threadIdx.x] += ss[threadIdx.x + o]; sq[threadIdx.x] += sq[threadIdx.x + o]; }
        __syncthreads();
    }
    if (threadIdx.x == 0) {
        int r = blockIdx.x & 31;
        atomicAdd(&g_red[OFF_X + 2 * r], ss[0]);
        atomicAdd(&g_red[OFF_X + 2 * r + 1], sq[0]);
    }
}

__global__ void kfin_d1(const float* __restrict__ w_d1, const float* __restrict__ g_d1,
                        const float* __restrict__ be_d1) {
    __shared__ float S[2];
    if (threadIdx.x == 0) {
        float s = 0.f, q = 0.f;
        for (int r = 0; r < 32; r++) { s += g_red[2 * r]; q += g_red[2 * r + 1]; }
        S[0] = s; S[1] = q;
    }
    __syncthreads();
    float mx = S[0] / (float)EE;
    float vx = S[1] / (float)EE - mx * mx;
    int h = threadIdx.x;
    float w = w_d1[h];
    float a = w * rsqrtf(vx * w * w + BN_EPS) * g_d1[h];
    g_coef[h] = a;
    g_coef[64 + h] = -mx * a + be_d1[h];
}

// d-path: d1 tile (80 edges x 64) in smem, then GEMM with w_d2 (via L1), fused stats
__global__ void kpassA(const float* __restrict__ x, const float* __restrict__ w_d2) {
    __shared__ float sD[80 * 64];
    __shared__ float ssum[64], ssq[64];
    int t = threadIdx.x;
    long e0 = (long)blockIdx.x * 80;

    for (int i = t; i < 80 * 64; i += 256) {
        int el = i >> 6, f = i & 63;
        float xv = x[e0 + el];
        sD[i] = sp(g_coef[f] * xv + g_coef[64 + f]);
    }
    if (t < 64) { ssum[t] = 0.f; ssq[t] = 0.f; }
    __syncthreads();

    int k = t & 63, q = t >> 6;
    float acc[20];
#pragma unroll
    for (int j = 0; j < 20; j++) acc[j] = 0.f;
#pragma unroll
    for (int f4 = 0; f4 < 16; f4++) {
        float4 w4 = __ldg((const float4*)&w_d2[k * 64 + f4 * 4]);
#pragma unroll
        for (int j = 0; j < 20; j++) {
            const float4 d = *(const float4*)&sD[(q + 4 * j) * 64 + f4 * 4];
            acc[j] += d.x * w4.x + d.y * w4.y + d.z * w4.z + d.w * w4.w;
        }
    }
    float s = 0.f, q2 = 0.f;
#pragma unroll
    for (int j = 0; j < 20; j++) {
        int el = q + 4 * j;
        g_d2p[(e0 + el) * 64 + k] = acc[j];
        s += acc[j]; q2 += acc[j] * acc[j];
    }
    atomicAdd(&ssum[k], s);
    atomicAdd(&ssq[k], q2);
    __syncthreads();
    if (t < 64) {
        int r = blockIdx.x & 31;
        atomicAdd(&g_red[OFF_D2 + r * 128 + t], ssum[t]);
        atomicAdd(&g_red[OFF_D2 + r * 128 + 64 + t], ssq[t]);
    }
}

// generic BN finalize: mean/var from replicated sums -> scale/shift into g_coef
__global__ void kfinbn(int redoff, int F, float cnt, const float* __restrict__ g,
                       const float* __restrict__ be, int coefoff) {
    int k = threadIdx.x;
    if (k >= F) return;
    float s = 0.f, q = 0.f;
    for (int r = 0; r < 32; r++) {
        s += g_red[redoff + r * 2 * F + k];
        q += g_red[redoff + r * 2 * F + F + k];
    }
    float m = s / cnt;
    float v = q / cnt - m * m;
    float sc = g[k] * rsqrtf(v + BN_EPS);
    g_coef[coefoff + k] = sc;
    g_coef[coefoff + 64 + k] = be[k] - m * sc;
}

__global__ void kinith(const int* __restrict__ node_type, const float* __restrict__ node_emb) {
    int i = blockIdx.x * 256 + threadIdx.x;   // N*64
    int n = i >> 6, k = i & 63;
    g_h[i] = node_emb[node_type[n] * 64 + k];
}

__global__ void kcopy() {
    int i = blockIdx.x * 256 + threadIdx.x;
    g_agg[i] = g_h[i];
}

// gconv edge kernel: 16 threads/edge, float4; fuses BN2 affine + edge_emb multiply
__global__ void kedge(const int* __restrict__ ei, const int* __restrict__ et,
                      const float* __restrict__ edge_emb) {
    int t = threadIdx.x;
    int e = blockIdx.x * 16 + (t >> 4);
    int f0 = (t & 15) * 4;
    int src = __ldg(&ei[e]);
    int dst = __ldg(&ei[EE + e]);
    int ty  = __ldg(&et[e]);
    float4 dp = *(const float4*)&g_d2p[(long)e * 64 + f0];
    float4 s2 = *(const float4*)&g_coef[128 + f0];
    float4 t2 = *(const float4*)&g_coef[192 + f0];
    float4 em = __ldg((const float4*)&edge_emb[ty * 64 + f0]);
    float4 hs = *(const float4*)&g_h[src * 64 + f0];
    float m0 = sp(hs.x + (dp.x * s2.x + t2.x) * em.x);
    float m1 = sp(hs.y + (dp.y * s2.y + t2.y) * em.y);
    float m2 = sp(hs.z + (dp.z * s2.z + t2.z) * em.z);
    float m3 = sp(hs.w + (dp.w * s2.w + t2.w) * em.w);
    float* o = &g_agg[dst * 64 + f0];
    atomicAdd(o + 0, m0);
    atomicAdd(o + 1, m1);
    atomicAdd(o + 2, m2);
    atomicAdd(o + 3, m3);
}

__global__ void knstat(int redoff) {
    int t = threadIdx.x;
    int f0 = (t & 15) * 4;
    float4 s = {0, 0, 0, 0}, q = {0, 0, 0, 0};
    for (int n = blockIdx.x * 16 + (t >> 4); n < NN; n += gridDim.x * 16) {
        float4 v = *(const float4*)&g_agg[n * 64 + f0];
        s.x += v.x; s.y += v.y; s.z += v.z; s.w += v.w;
        q.x += v.x * v.x; q.y += v.y * v.y; q.z += v.z * v.z; q.w += v.w * v.w;
    }
    __shared__ float ssum[64], ssq[64];
    if (t < 64) { ssum[t] = 0.f; ssq[t] = 0.f; }
    __syncthreads();
    atomicAdd(&ssum[f0 + 0], s.x); atomicAdd(&ssum[f0 + 1], s.y);
    atomicAdd(&ssum[f0 + 2], s.z); atomicAdd(&ssum[f0 + 3], s.w);
    atomicAdd(&ssq[f0 + 0], q.x); atomicAdd(&ssq[f0 + 1], q.y);
    atomicAdd(&ssq[f0 + 2], q.z); atomicAdd(&ssq[f0 + 3], q.w);
    __syncthreads();
    if (t < 64) {
        int r = blockIdx.x & 31;
        atomicAdd(&g_red[redoff + r * 128 + t], ssum[t]);
        atomicAdd(&g_red[redoff + r * 128 + 64 + t], ssq[t]);
    }
}

__global__ void kapply(int coefoff, int doact, int dohg, const int* __restrict__ batch) {
    int i = blockIdx.x * 256 + threadIdx.x;  // N*16
    int n = i >> 4;
    int f0 = (i & 15) * 4;
    float4 v  = *(const float4*)&g_agg[n * 64 + f0];
    float4 sc = *(const float4*)&g_coef[coefoff + f0];
    float4 sh = *(const float4*)&g_coef[coefoff + 64 + f0];
    v.x = v.x * sc.x + sh.x; v.y = v.y * sc.y + sh.y;
    v.z = v.z * sc.z + sh.z; v.w = v.w * sc.w + sh.w;
    if (doact) { v.x = sp(v.x); v.y = sp(v.y); v.z = sp(v.z); v.w = sp(v.w); }
    *(float4*)&g_h[n * 64 + f0] = v;
    if (dohg) {
        int b = batch[n];
        float* o = &g_hg[b * 64 + f0];
        atomicAdd(o + 0, v.x); atomicAdd(o + 1, v.y);
        atomicAdd(o + 2, v.z); atomicAdd(o + 3, v.w);
    }
}

// out MLP stage 1: y1 = [h | hg[batch]] @ w_o1^T + b_o1, fused stats
__global__ void kstage1(const int* __restrict__ batch, const float* __restrict__ w_o1,
                        const float* __restrict__ b_o1) {
    __shared__ float snf[4][128];
    __shared__ float ssum[64], ssq[64];
    int t = threadIdx.x, q = t >> 6, k = t & 63;
    int n = blockIdx.x * 4 + q;
    snf[q][k]      = g_h[n * 64 + k];
    snf[q][64 + k] = g_hg[batch[n] * 64 + k];
    if (t < 64) { ssum[t] = 0.f; ssq[t] = 0.f; }
    __syncthreads();
    float acc = b_o1[k];
#pragma unroll
    for (int j4 = 0; j4 < 32; j4++) {
        float4 w4 = __ldg((const float4*)&w_o1[k * 128 + j4 * 4]);
        float4 v = *(const float4*)&snf[q][j4 * 4];
        acc += v.x * w4.x + v.y * w4.y + v.z * w4.z + v.w * w4.w;
    }
    g_y1[n * 64 + k] = acc;
    atomicAdd(&ssum[k], acc);
    atomicAdd(&ssq[k], acc * acc);
    __syncthreads();
    if (t < 64) {
        int r = blockIdx.x & 31;
        atomicAdd(&g_red[OFF_O1 + r * 128 + t], ssum[t]);
        atomicAdd(&g_red[OFF_O1 + r * 128 + 64 + t], ssq[t]);
    }
}

// stage 2: y2 = act(BN(y1)) @ w_o2^T + b_o2, fused stats
__global__ void kstage2(const float* __restrict__ w_o2, const float* __restrict__ b_o2) {
    __shared__ float sv[4][64];
    __shared__ float ssum[32], ssq[32];
    int t = threadIdx.x, q = t >> 5, k = t & 31;
    int n = blockIdx.x * 4 + q;
    {
        float a = g_y1[n * 64 + k]      * g_coef[640 + k]      + g_coef[704 + k];
        float b = g_y1[n * 64 + 32 + k] * g_coef[640 + 32 + k] + g_coef[704 + 32 + k];
        sv[q][k] = sp(a);
        sv[q][32 + k] = sp(b);
    }
    if (t < 32) { ssum[t] = 0.f; ssq[t] = 0.f; }
    __syncthreads();
    float acc = b_o2[k];
#pragma unroll
    for (int j4 = 0; j4 < 16; j4++) {
        float4 w4 = __ldg((const float4*)&w_o2[k * 64 + j4 * 4]);
        float4 v = *(const float4*)&sv[q][j4 * 4];
        acc += v.x * w4.x + v.y * w4.y + v.z * w4.z + v.w * w4.w;
    }
    g_y2[n * 32 + k] = acc;
    atomicAdd(&ssum[k], acc);
    atomicAdd(&ssq[k], acc * acc);
    __syncthreads();
    if (t < 32) {
        int r = blockIdx.x & 31;
        atomicAdd(&g_red[OFF_O2 + r * 64 + t], ssum[t]);
        atomicAdd(&g_red[OFF_O2 + r * 64 + 32 + t], ssq[t]);
    }
}

// stage 3: out = act(BN(y2)) @ w_o3^T + b_o3 ; write split halves
__global__ void kstage3(const float* __restrict__ w_o3, const float* __restrict__ b_o3,
                        float* __restrict__ out) {
    __shared__ float sv[2][32];
    int t = threadIdx.x;
    int n2 = blockIdx.x * 2;
    if (t < 64) {
        int q = t >> 5, k = t & 31;
        float a = g_y2[(n2 + q) * 32 + k] * g_coef[768 + k] + g_coef[832 + k];
        sv[q][k] = sp(a);
    }
    __syncthreads();
    int q = t >> 7, c = t & 127;
    int n = n2 + q;
    float acc = b_o3[c];
#pragma unroll
    for (int j4 = 0; j4 < 8; j4++) {
        float4 w4 = __ldg((const float4*)&w_o3[c * 32 + j4 * 4]);
        float4 v = *(const float4*)&sv[q][j4 * 4];
        acc += v.x * w4.x + v.y * w4.y + v.z * w4.z + v.w * w4.w;
    }
    if (c < 64) out[(long)n * 64 + c] = acc;
    else        out[(long)NN * 64 + (long)n * 64 + (c - 64)] = acc;
}

// ---------------- launch ----------------
extern "C" void kernel_launch(void* const* d_in, const int* in_sizes, int n_in,
                              void* d_out, int out_size) {
    const float* x         = (const float*)d_in[0];
    const int*   node_type = (const int*)d_in[1];
    const int*   edge_type = (const int*)d_in[2];
    const int*   edge_index= (const int*)d_in[3];
    const int*   batch     = (const int*)d_in[4];
    const float* node_emb  = (const float*)d_in[5];
    const float* edge_emb  = (const float*)d_in[6];
    const float* w_d1      = (const float*)d_in[7];
    const float* g_d1      = (const float*)d_in[9];
    const float* be_d1     = (const float*)d_in[10];
    const float* w_d2      = (const float*)d_in[11];
    const float* g_d2      = (const float*)d_in[13];
    const float* be_d2     = (const float*)d_in[14];
    const float* g_c1      = (const float*)d_in[15];
    const float* be_c1     = (const float*)d_in[16];
    const float* g_c2      = (const float*)d_in[17];
    const float* be_c2     = (const float*)d_in[18];
    const float* g_c3      = (const float*)d_in[19];
    const float* be_c3     = (const float*)d_in[20];
    const float* w_o1      = (const float*)d_in[21];
    const float* b_o1      = (const float*)d_in[22];
    const float* g_o1      = (const float*)d_in[23];
    const float* be_o1     = (const float*)d_in[24];
    const float* w_o2      = (const float*)d_in[25];
    const float* b_o2      = (const float*)d_in[26];
    const float* g_o2      = (const float*)d_in[27];
    const float* be_o2     = (const float*)d_in[28];
    const float* w_o3      = (const float*)d_in[29];
    const float* b_o3      = (const float*)d_in[30];

    kzero<<<125, 256>>>();
    kxstat<<<1024, 256>>>(x);
    kfin_d1<<<1, 64>>>(w_d1, g_d1, be_d1);
    kpassA<<<15625, 256>>>(x, w_d2);                           // E/80 blocks
    kfinbn<<<1, 64>>>(OFF_D2, 64, (float)EE, g_d2, be_d2, 128);
    kinith<<<12500, 256>>>(node_type, node_emb);

    const int   statoff[3] = {OFF_C1, OFF_C2, OFF_C3};
    const int   coefoff[3] = {256, 384, 512};
    const float* gs[3]  = {g_c1, g_c2, g_c3};
    const float* bes[3] = {be_c1, be_c2, be_c3};
    for (int l = 0; l < 3; l++) {
        kcopy<<<12500, 256>>>();
        kedge<<<78125, 256>>>(edge_index, edge_type, edge_emb);  // E/16 blocks
        knstat<<<256, 256>>>(statoff[l]);
        kfinbn<<<1, 64>>>(statoff[l], 64, (float)NN, gs[l], bes[l], coefoff[l]);
        kapply<<<3125, 256>>>(coefoff[l], (l < 2) ? 1 : 0, (l == 2) ? 1 : 0, batch);
    }

    kstage1<<<12500, 256>>>(batch, w_o1, b_o1);
    kfinbn<<<1, 64>>>(OFF_O1, 64, (float)NN, g_o1, be_o1, 640);
    kstage2<<<12500, 128>>>(w_o2, b_o2);
    kfinbn<<<1, 64>>>(OFF_O2, 32, (float)NN, g_o2, be_o2, 768);
    kstage3<<<25000, 256>>>(w_o3, b_o3, (float*)d_out);
}

// round 2
// speedup vs baseline: 1.8303x; 1.8303x over previous
#include <cuda_runtime.h>

#define NN 50000
#define EE 1250000
#define HH 64
#define BB 500
#define BN_EPS 1e-5f

#define NB 2048
#define XLO (-8.0f)
#define INVH 128.0f          // NB / (XHI-XLO) = 2048/16
#define H_STEP 0.0078125f    // 16/2048

// ---------------- device scratch ----------------
__device__ float g_T[(NB + 1) * HH];     // piecewise-linear table F_k(x), 512KB
__device__ float g_hist[5 * NB];         // c0,c1,s0,s1,s2
__device__ float g_h[NN * HH];
__device__ float g_agg[NN * HH];
__device__ float g_hg[BB * HH];
__device__ float g_y1[NN * 64];
__device__ float g_y2[NN * 32];
__device__ float g_red[22592];
__device__ float g_coef[1024];

#define OFF_X   0
#define OFF_D2  64
#define OFF_C1  4160
#define OFF_C2  8256
#define OFF_C3  12352
#define OFF_O1  16448
#define OFF_O2  20544

__device__ __forceinline__ float sp(float x) {
    float t, l;
    asm("ex2.approx.ftz.f32 %0, %1;" : "=f"(t) : "f"(x * 1.44269504f));
    asm("lg2.approx.f32 %0, %1;" : "=f"(l) : "f"(1.0f + t));
    float r = l * 0.69314718f;
    return x > 20.0f ? x : r;
}

// ---------------- kernels ----------------

__global__ void kzero() {
    int i = blockIdx.x * 256 + threadIdx.x;
    if (i < 22592) g_red[i] = 0.0f;
    if (i < BB * HH) g_hg[i] = 0.0f;
    if (i < 5 * NB) g_hist[i] = 0.0f;
}

// histogram over x: bin weights + interp-square moments + raw x stats
__global__ void khist(const float* __restrict__ x) {
    __shared__ float hc0[NB], hc1[NB], hs0[NB], hs1[NB], hs2[NB];
    __shared__ float sxs[2];
    int t = threadIdx.x;
    for (int i = t; i < NB; i += 256) { hc0[i] = 0; hc1[i] = 0; hs0[i] = 0; hs1[i] = 0; hs2[i] = 0; }
    if (t < 2) sxs[t] = 0.f;
    __syncthreads();

    float sx = 0.f, sxx = 0.f;
    for (int i = blockIdx.x * 256 + t; i < EE; i += gridDim.x * 256) {
        float v = x[i];
        sx += v; sxx += v * v;
        float u = (v - XLO) * INVH;
        u = fminf(fmaxf(u, 0.0f), (float)NB);
        int b = (int)u; if (b > NB - 1) b = NB - 1;
        float w = u - (float)b;
        float omw = 1.0f - w;
        atomicAdd(&hc0[b], omw);
        atomicAdd(&hc1[b], w);
        atomicAdd(&hs0[b], omw * omw);
        atomicAdd(&hs1[b], w * omw);
        atomicAdd(&hs2[b], w * w);
    }
    atomicAdd(&sxs[0], sx);
    atomicAdd(&sxs[1], sxx);
    __syncthreads();
    for (int i = t; i < NB; i += 256) {
        if (hc0[i] != 0.f) atomicAdd(&g_hist[i], hc0[i]);
        if (hc1[i] != 0.f) atomicAdd(&g_hist[NB + i], hc1[i]);
        if (hs0[i] != 0.f) atomicAdd(&g_hist[2 * NB + i], hs0[i]);
        if (hs1[i] != 0.f) atomicAdd(&g_hist[3 * NB + i], hs1[i]);
        if (hs2[i] != 0.f) atomicAdd(&g_hist[4 * NB + i], hs2[i]);
    }
    if (t == 0) {
        int r = blockIdx.x & 31;
        atomicAdd(&g_red[OFF_X + 2 * r], sxs[0]);
        atomicAdd(&g_red[OFF_X + 2 * r + 1], sxs[1]);
    }
}

__global__ void kfin_d1(const float* __restrict__ w_d1, const float* __restrict__ g_d1,
                        const float* __restrict__ be_d1) {
    __shared__ float S[2];
    if (threadIdx.x == 0) {
        float s = 0.f, q = 0.f;
        for (int r = 0; r < 32; r++) { s += g_red[2 * r]; q += g_red[2 * r + 1]; }
        S[0] = s; S[1] = q;
    }
    __syncthreads();
    float mx = S[0] / (float)EE;
    float vx = S[1] / (float)EE - mx * mx;
    int h = threadIdx.x;
    float w = w_d1[h];
    float a = w * rsqrtf(vx * w * w + BN_EPS) * g_d1[h];
    g_coef[h] = a;
    g_coef[64 + h] = -mx * a + be_d1[h];
}

// build table T[b][k] = sum_f sp(a_f*x_b + c_f) * w_d2[k][f]
__global__ void ktable(const float* __restrict__ w_d2) {
    __shared__ float spv[64];
    int b = blockIdx.x, k = threadIdx.x;
    float xb = XLO + (float)b * H_STEP;
    spv[k] = sp(g_coef[k] * xb + g_coef[64 + k]);
    __syncthreads();
    float acc = 0.f;
#pragma unroll 8
    for (int f = 0; f < 64; f++) acc += spv[f] * __ldg(&w_d2[k * 64 + f]);
    g_T[b * 64 + k] = acc;
}

// exact stats of interpolated d2 from histogram moments
__global__ void kd2stat() {
    int k = threadIdx.x;
    int b0 = blockIdx.x * 128;
    float s = 0.f, q = 0.f;
    float tp = g_T[b0 * 64 + k];
    for (int j = 0; j < 128; j++) {
        int b = b0 + j;
        float tn = g_T[(b + 1) * 64 + k];
        float c0 = g_hist[b], c1 = g_hist[NB + b];
        float s0 = g_hist[2 * NB + b], s1 = g_hist[3 * NB + b], s2v = g_hist[4 * NB + b];
        s += c0 * tp + c1 * tn;
        q += s0 * tp * tp + 2.0f * s1 * tp * tn + s2v * tn * tn;
        tp = tn;
    }
    int r = blockIdx.x & 31;
    atomicAdd(&g_red[OFF_D2 + r * 128 + k], s);
    atomicAdd(&g_red[OFF_D2 + r * 128 + 64 + k], q);
}

__global__ void kfinbn(int redoff, int F, float cnt, const float* __restrict__ g,
                       const float* __restrict__ be, int coefoff) {
    int k = threadIdx.x;
    if (k >= F) return;
    float s = 0.f, q = 0.f;
    for (int r = 0; r < 32; r++) {
        s += g_red[redoff + r * 2 * F + k];
        q += g_red[redoff + r * 2 * F + F + k];
    }
    float m = s / cnt;
    float v = q / cnt - m * m;
    float sc = g[k] * rsqrtf(v + BN_EPS);
    g_coef[coefoff + k] = sc;
    g_coef[coefoff + 64 + k] = be[k] - m * sc;
}

// fold BN2 affine into the table (linear -> commutes with interpolation)
__global__ void ktaffine() {
    int i = blockIdx.x * 256 + threadIdx.x;
    if (i >= (NB + 1) * 64) return;
    int k = i & 63;
    g_T[i] = g_T[i] * g_coef[128 + k] + g_coef[192 + k];
}

__global__ void kinith(const int* __restrict__ node_type, const float* __restrict__ node_emb) {
    int i = blockIdx.x * 256 + threadIdx.x;
    int n = i >> 6, k = i & 63;
    g_h[i] = node_emb[node_type[n] * 64 + k];
}

__global__ void kcopy() {
    int i = blockIdx.x * 256 + threadIdx.x;
    g_agg[i] = g_h[i];
}

// gconv edge kernel: ea from table interp, vectorized reduction scatter
__global__ void kedge(const int* __restrict__ ei, const int* __restrict__ et,
                      const float* __restrict__ x, const float* __restrict__ edge_emb) {
    int t = threadIdx.x;
    int e = blockIdx.x * 16 + (t >> 4);
    int f0 = (t & 15) * 4;
    int src = __ldg(&ei[e]);
    int dst = __ldg(&ei[EE + e]);
    int ty  = __ldg(&et[e]);
    float xv = __ldg(&x[e]);
    float u = (xv - XLO) * INVH;
    u = fminf(fmaxf(u, 0.0f), (float)NB);
    int b = (int)u; if (b > NB - 1) b = NB - 1;
    float w = u - (float)b;

    float4 t0 = *(const float4*)&g_T[b * 64 + f0];
    float4 t1 = *(const float4*)&g_T[(b + 1) * 64 + f0];
    float4 em = __ldg((const float4*)&edge_emb[ty * 64 + f0]);
    float4 hs = *(const float4*)&g_h[src * 64 + f0];

    float d0 = fmaf(w, t1.x - t0.x, t0.x);
    float d1 = fmaf(w, t1.y - t0.y, t0.y);
    float d2 = fmaf(w, t1.z - t0.z, t0.z);
    float d3 = fmaf(w, t1.w - t0.w, t0.w);

    float m0 = sp(hs.x + d0 * em.x);
    float m1 = sp(hs.y + d1 * em.y);
    float m2 = sp(hs.z + d2 * em.z);
    float m3 = sp(hs.w + d3 * em.w);

    float* o = &g_agg[dst * 64 + f0];
    asm volatile("red.global.add.v4.f32 [%0], {%1, %2, %3, %4};"
                 :: "l"(o), "f"(m0), "f"(m1), "f"(m2), "f"(m3) : "memory");
}

__global__ void knstat(int redoff) {
    int t = threadIdx.x;
    int f0 = (t & 15) * 4;
    float4 s = {0, 0, 0, 0}, q = {0, 0, 0, 0};
    for (int n = blockIdx.x * 16 + (t >> 4); n < NN; n += gridDim.x * 16) {
        float4 v = *(const float4*)&g_agg[n * 64 + f0];
        s.x += v.x; s.y += v.y; s.z += v.z; s.w += v.w;
        q.x += v.x * v.x; q.y += v.y * v.y; q.z += v.z * v.z; q.w += v.w * v.w;
    }
    __shared__ float ssum[64], ssq[64];
    if (t < 64) { ssum[t] = 0.f; ssq[t] = 0.f; }
    __syncthreads();
    atomicAdd(&ssum[f0 + 0], s.x); atomicAdd(&ssum[f0 + 1], s.y);
    atomicAdd(&ssum[f0 + 2], s.z); atomicAdd(&ssum[f0 + 3], s.w);
    atomicAdd(&ssq[f0 + 0], q.x); atomicAdd(&ssq[f0 + 1], q.y);
    atomicAdd(&ssq[f0 + 2], q.z); atomicAdd(&ssq[f0 + 3], q.w);
    __syncthreads();
    if (t < 64) {
        int r = blockIdx.x & 31;
        atomicAdd(&g_red[redoff + r * 128 + t], ssum[t]);
        atomicAdd(&g_red[redoff + r * 128 + 64 + t], ssq[t]);
    }
}

__global__ void kapply(int coefoff, int doact, int dohg, const int* __restrict__ batch) {
    int i = blockIdx.x * 256 + threadIdx.x;
    int n = i >> 4;
    int f0 = (i & 15) * 4;
    float4 v  = *(const float4*)&g_agg[n * 64 + f0];
    float4 sc = *(const float4*)&g_coef[coefoff + f0];
    float4 sh = *(const float4*)&g_coef[coefoff + 64 + f0];
    v.x = v.x * sc.x + sh.x; v.y = v.y * sc.y + sh.y;
    v.z = v.z * sc.z + sh.z; v.w = v.w * sc.w + sh.w;
    if (doact) { v.x = sp(v.x); v.y = sp(v.y); v.z = sp(v.z); v.w = sp(v.w); }
    *(float4*)&g_h[n * 64 + f0] = v;
    if (dohg) {
        int b = batch[n];
        float* o = &g_hg[b * 64 + f0];
        asm volatile("red.global.add.v4.f32 [%0], {%1, %2, %3, %4};"
                     :: "l"(o), "f"(v.x), "f"(v.y), "f"(v.z), "f"(v.w) : "memory");
    }
}

__global__ void kstage1(const int* __restrict__ batch, const float* __restrict__ w_o1,
                        const float* __restrict__ b_o1) {
    __shared__ float snf[4][128];
    __shared__ float ssum[64], ssq[64];
    int t = threadIdx.x, q = t >> 6, k = t & 63;
    int n = blockIdx.x * 4 + q;
    snf[q][k]      = g_h[n * 64 + k];
    snf[q][64 + k] = g_hg[batch[n] * 64 + k];
    if (t < 64) { ssum[t] = 0.f; ssq[t] = 0.f; }
    __syncthreads();
    float acc = b_o1[k];
#pragma unroll
    for (int j4 = 0; j4 < 32; j4++) {
        float4 w4 = __ldg((const float4*)&w_o1[k * 128 + j4 * 4]);
        float4 v = *(const float4*)&snf[q][j4 * 4];
        acc += v.x * w4.x + v.y * w4.y + v.z * w4.z + v.w * w4.w;
    }
    g_y1[n * 64 + k] = acc;
    atomicAdd(&ssum[k], acc);
    atomicAdd(&ssq[k], acc * acc);
    __syncthreads();
    if (t < 64) {
        int r = blockIdx.x & 31;
        atomicAdd(&g_red[OFF_O1 + r * 128 + t], ssum[t]);
        atomicAdd(&g_red[OFF_O1 + r * 128 + 64 + t], ssq[t]);
    }
}

__global__ void kstage2(const float* __restrict__ w_o2, const float* __restrict__ b_o2) {
    __shared__ float sv[4][64];
    __shared__ float ssum[32], ssq[32];
    int t = threadIdx.x, q = t >> 5, k = t & 31;
    int n = blockIdx.x * 4 + q;
    {
        float a = g_y1[n * 64 + k]      * g_coef[640 + k]      + g_coef[704 + k];
        float b = g_y1[n * 64 + 32 + k] * g_coef[640 + 32 + k] + g_coef[704 + 32 + k];
        sv[q][k] = sp(a);
        sv[q][32 + k] = sp(b);
    }
    if (t < 32) { ssum[t] = 0.f; ssq[t] = 0.f; }
    __syncthreads();
    float acc = b_o2[k];
#pragma unroll
    for (int j4 = 0; j4 < 16; j4++) {
        float4 w4 = __ldg((const float4*)&w_o2[k * 64 + j4 * 4]);
        float4 v = *(const float4*)&sv[q][j4 * 4];
        acc += v.x * w4.x + v.y * w4.y + v.z * w4.z + v.w * w4.w;
    }
    g_y2[n * 32 + k] = acc;
    atomicAdd(&ssum[k], acc);
    atomicAdd(&ssq[k], acc * acc);
    __syncthreads();
    if (t < 32) {
        int r = blockIdx.x & 31;
        atomicAdd(&g_red[OFF_O2 + r * 64 + t], ssum[t]);
        atomicAdd(&g_red[OFF_O2 + r * 64 + 32 + t], ssq[t]);
    }
}

__global__ void kstage3(const float* __restrict__ w_o3, const float* __restrict__ b_o3,
                        float* __restrict__ out) {
    __shared__ float sv[2][32];
    int t = threadIdx.x;
    int n2 = blockIdx.x * 2;
    if (t < 64) {
        int q = t >> 5, k = t & 31;
        float a = g_y2[(n2 + q) * 32 + k] * g_coef[768 + k] + g_coef[832 + k];
        sv[q][k] = sp(a);
    }
    __syncthreads();
    int q = t >> 7, c = t & 127;
    int n = n2 + q;
    float acc = b_o3[c];
#pragma unroll
    for (int j4 = 0; j4 < 8; j4++) {
        float4 w4 = __ldg((const float4*)&w_o3[c * 32 + j4 * 4]);
        float4 v = *(const float4*)&sv[q][j4 * 4];
        acc += v.x * w4.x + v.y * w4.y + v.z * w4.z + v.w * w4.w;
    }
    if (c < 64) out[(long)n * 64 + c] = acc;
    else        out[(long)NN * 64 + (long)n * 64 + (c - 64)] = acc;
}

// ---------------- launch ----------------
extern "C" void kernel_launch(void* const* d_in, const int* in_sizes, int n_in,
                              void* d_out, int out_size) {
    const float* x         = (const float*)d_in[0];
    const int*   node_type = (const int*)d_in[1];
    const int*   edge_type = (const int*)d_in[2];
    const int*   edge_index= (const int*)d_in[3];
    const int*   batch     = (const int*)d_in[4];
    const float* node_emb  = (const float*)d_in[5];
    const float* edge_emb  = (const float*)d_in[6];
    const float* w_d1      = (const float*)d_in[7];
    const float* g_d1      = (const float*)d_in[9];
    const float* be_d1     = (const float*)d_in[10];
    const float* w_d2      = (const float*)d_in[11];
    const float* g_d2      = (const float*)d_in[13];
    const float* be_d2     = (const float*)d_in[14];
    const float* g_c1      = (const float*)d_in[15];
    const float* be_c1     = (const float*)d_in[16];
    const float* g_c2      = (const float*)d_in[17];
    const float* be_c2     = (const float*)d_in[18];
    const float* g_c3      = (const float*)d_in[19];
    const float* be_c3     = (const float*)d_in[20];
    const float* w_o1      = (const float*)d_in[21];
    const float* b_o1      = (const float*)d_in[22];
    const float* g_o1      = (const float*)d_in[23];
    const float* be_o1     = (const float*)d_in[24];
    const float* w_o2      = (const float*)d_in[25];
    const float* b_o2      = (const float*)d_in[26];
    const float* g_o2      = (const float*)d_in[27];
    const float* be_o2     = (const float*)d_in[28];
    const float* w_o3      = (const float*)d_in[29];
    const float* b_o3      = (const float*)d_in[30];

    kzero<<<125, 256>>>();
    khist<<<256, 256>>>(x);
    kfin_d1<<<1, 64>>>(w_d1, g_d1, be_d1);
    ktable<<<NB + 1, 64>>>(w_d2);
    kd2stat<<<16, 64>>>();
    kfinbn<<<1, 64>>>(OFF_D2, 64, (float)EE, g_d2, be_d2, 128);
    ktaffine<<<((NB + 1) * 64 + 255) / 256, 256>>>();
    kinith<<<12500, 256>>>(node_type, node_emb);

    const int   statoff[3] = {OFF_C1, OFF_C2, OFF_C3};
    const int   coefoff[3] = {256, 384, 512};
    const float* gs[3]  = {g_c1, g_c2, g_c3};
    const float* bes[3] = {be_c1, be_c2, be_c3};
    for (int l = 0; l < 3; l++) {
        kcopy<<<12500, 256>>>();
        kedge<<<78125, 256>>>(edge_index, edge_type, x, edge_emb);
        knstat<<<256, 256>>>(statoff[l]);
        kfinbn<<<1, 64>>>(statoff[l], 64, (float)NN, gs[l], bes[l], coefoff[l]);
        kapply<<<3125, 256>>>(coefoff[l], (l < 2) ? 1 : 0, (l == 2) ? 1 : 0, batch);
    }

    kstage1<<<12500, 256>>>(batch, w_o1, b_o1);
    kfinbn<<<1, 64>>>(OFF_O1, 64, (float)NN, g_o1, be_o1, 640);
    kstage2<<<12500, 128>>>(w_o2, b_o2);
    kfinbn<<<1, 64>>>(OFF_O2, 32, (float)NN, g_o2, be_o2, 768);
    kstage3<<<25000, 256>>>(w_o3, b_o3, (float*)d_out);
}